// round 14
// baseline (speedup 1.0000x reference)
#include <cuda_runtime.h>
#include <cuda_fp16.h>
#include <math.h>
#include <stdint.h>

// Problem constants
#define Bn 16384
#define Dn 1024
#define En 6
#define Hn 256
#define TMk 128
#define BD 16777216

// ---------------- device scratch ----------------
__device__ double g_load_sums[En];
__device__ int    g_expert_count[En];
__device__ int    g_expert_tok[En * Bn];   // token | (slot<<30)
__device__ float  g_expert_wt[En * Bn];
__device__ float  g_WrT[En * Dn];          // router weight transposed [e][d]
__device__ __half g_Xh[Bn * Dn];           // x (fp16)
__device__ __half g_W1T[En * Hn * Dn];     // [e][h][d]  (K-major, n=h)
__device__ __half g_W2T[En * Dn * Hn];     // [e][d][h]  (K-major, n=d)
__device__ __half g_bufh[2u * Bn * Dn];    // per-slot weighted expert outputs (fp16)

// ---------------- helpers ----------------
__device__ __forceinline__ uint32_t smem_u32(const void* p) {
    uint32_t a;
    asm("{ .reg .u64 t; cvta.to.shared.u64 t, %1; cvt.u32.u64 %0, t; }" : "=r"(a) : "l"(p));
    return a;
}
__device__ __forceinline__ uint32_t sw(uint32_t o) { return o ^ ((o >> 3) & 0x70); }
__device__ __forceinline__ uint32_t cvt2h(float lo, float hi) {
    uint32_t r;
    asm("cvt.rn.f16x2.f32 %0, %1, %2;" : "=r"(r) : "f"(hi), "f"(lo));
    return r;
}
__device__ __forceinline__ void ldsm4(uint32_t* r, uint32_t a) {
    asm volatile("ldmatrix.sync.aligned.m8n8.x4.shared.b16 {%0,%1,%2,%3}, [%4];"
                 : "=r"(r[0]), "=r"(r[1]), "=r"(r[2]), "=r"(r[3]) : "r"(a));
}
__device__ __forceinline__ void mma_h(float* c, const uint32_t* a, uint32_t b0, uint32_t b1) {
    asm volatile(
        "mma.sync.aligned.m16n8k16.row.col.f32.f16.f16.f32 "
        "{%0,%1,%2,%3}, {%4,%5,%6,%7}, {%8,%9}, {%0,%1,%2,%3};"
        : "+f"(c[0]), "+f"(c[1]), "+f"(c[2]), "+f"(c[3])
        : "r"(a[0]), "r"(a[1]), "r"(a[2]), "r"(a[3]), "r"(b0), "r"(b1));
}
__device__ __forceinline__ void cpa(uint32_t dst, const void* src) {
    asm volatile("cp.async.cg.shared.global [%0], [%1], 16;" :: "r"(dst), "l"(src));
}
__device__ __forceinline__ void cp_commit() { asm volatile("cp.async.commit_group;"); }
__device__ __forceinline__ void cp_wait0()  { asm volatile("cp.async.wait_group 0;"); }
__device__ __forceinline__ void cp_wait1()  { asm volatile("cp.async.wait_group 1;"); }
__device__ __forceinline__ float gelu(float t) {
    return 0.5f * t * (1.0f + erff(t * 0.70710678118654752f));
}

// ---------------- kernel: zero counters + transpose Wr ----------------
__global__ void prep_small(const float* __restrict__ Wr) {
    int i = blockIdx.x * 256 + threadIdx.x;
    if (i < En) {
        g_load_sums[i] = 0.0;
        g_expert_count[i] = 0;
    }
    if (i < Dn * En) {
        int d = i / En, e = i % En;
        g_WrT[e * Dn + d] = Wr[i];
    }
}

// ---------------- kernel: weight transpose -> fp16 ----------------
__global__ void transpose_half_kernel(const float* __restrict__ src, int R, int C, int which) {
    __shared__ float tile[32][33];
    int e = blockIdx.z;
    int c0 = blockIdx.x * 32, r0 = blockIdx.y * 32;
    const float* s = src + (size_t)e * R * C;
    __half* d = (which == 0 ? g_W1T : g_W2T) + (size_t)e * R * C;
#pragma unroll
    for (int i = 0; i < 32; i += 8)
        tile[threadIdx.y + i][threadIdx.x] = s[(size_t)(r0 + threadIdx.y + i) * C + c0 + threadIdx.x];
    __syncthreads();
#pragma unroll
    for (int i = 0; i < 32; i += 8) {
        size_t o = (size_t)(c0 + threadIdx.y + i) * R + r0 + threadIdx.x;
        d[o] = __float2half_rn(tile[threadIdx.x][threadIdx.y + i]);
    }
}

// ---------------- kernel: fused router + x->fp16, block-aggregated atomics ----------------
__global__ void __launch_bounds__(512, 2) router_split_kernel(
    const float* __restrict__ x, const float* __restrict__ br)
{
    __shared__ float wsh[En * Dn];        // 24KB
    __shared__ float sm_p[16][En];
    __shared__ int   sm_pick[16][2];
    __shared__ float sm_w[16][2];

    int tid = threadIdx.x;
    int warp = tid >> 5, lane = tid & 31;
    for (int i = tid * 4; i < En * Dn; i += 2048)
        *(float4*)(wsh + i) = *(const float4*)(g_WrT + i);
    __syncthreads();

    int t = blockIdx.x * 16 + warp;
    {
        const float* xr = x + (size_t)t * Dn;
        char* dh = (char*)g_Xh + (size_t)t * Dn * 2;

        float acc[En];
#pragma unroll
        for (int e = 0; e < En; e++) acc[e] = 0.0f;

#pragma unroll
        for (int half = 0; half < 2; half++) {
            float4 v[4];
#pragma unroll
            for (int jj = 0; jj < 4; jj++)
                v[jj] = *(const float4*)(xr + (lane + 32 * (half * 4 + jj)) * 4);
#pragma unroll
            for (int jj = 0; jj < 4; jj++) {
                int d0 = (lane + 32 * (half * 4 + jj)) * 4;
#pragma unroll
                for (int e = 0; e < En; e++) {
                    float4 w = *(const float4*)(wsh + e * Dn + d0);
                    acc[e] = fmaf(v[jj].x, w.x, acc[e]);
                    acc[e] = fmaf(v[jj].y, w.y, acc[e]);
                    acc[e] = fmaf(v[jj].z, w.z, acc[e]);
                    acc[e] = fmaf(v[jj].w, w.w, acc[e]);
                }
                *(uint2*)(dh + d0 * 2) = make_uint2(cvt2h(v[jj].x, v[jj].y),
                                                    cvt2h(v[jj].z, v[jj].w));
            }
        }
#pragma unroll
        for (int off = 16; off > 0; off >>= 1)
#pragma unroll
            for (int e = 0; e < En; e++)
                acc[e] += __shfl_xor_sync(0xffffffffu, acc[e], off);

        if (lane == 0) {
            float p[En];
            float m = -1e30f;
#pragma unroll
            for (int e = 0; e < En; e++) { p[e] = acc[e] + br[e]; m = fmaxf(m, p[e]); }
            float s = 0.0f;
#pragma unroll
            for (int e = 0; e < En; e++) { p[e] = expf(p[e] - m); s += p[e]; }
            float inv = 1.0f / s;
#pragma unroll
            for (int e = 0; e < En; e++) {
                p[e] = 0.9f * p[e] * inv + (0.1f / 6.0f);
                sm_p[warp][e] = p[e];
            }
            int i0 = 0;
#pragma unroll
            for (int e = 1; e < En; e++) if (p[e] > p[i0]) i0 = e;
            int i1 = (i0 == 0) ? 1 : 0;
#pragma unroll
            for (int e = 0; e < En; e++) if (e != i0 && p[e] > p[i1]) i1 = e;
            sm_pick[warp][0] = i0; sm_pick[warp][1] = i1;
            sm_w[warp][0] = p[i0]; sm_w[warp][1] = p[i1];
        }
    }
    __syncthreads();

    if (tid < En) {
        int e = tid;
        double s = 0.0;
        int cnt = 0;
#pragma unroll
        for (int w = 0; w < 16; w++) {
            s += (double)sm_p[w][e];
            cnt += (sm_pick[w][0] == e) + (sm_pick[w][1] == e);
        }
        atomicAdd(&g_load_sums[e], s);
        int base = atomicAdd(&g_expert_count[e], cnt);
#pragma unroll
        for (int w = 0; w < 16; w++) {
            int tt = blockIdx.x * 16 + w;
            if (sm_pick[w][0] == e) {
                g_expert_tok[e * Bn + base] = tt;
                g_expert_wt[e * Bn + base] = sm_w[w][0];
                base++;
            }
            if (sm_pick[w][1] == e) {
                g_expert_tok[e * Bn + base] = tt | (1 << 30);
                g_expert_wt[e * Bn + base] = sm_w[w][1];
                base++;
            }
        }
    }
}

// ---------------- kernel: aux scalar ----------------
__global__ void aux_kernel(float* __restrict__ out_aux) {
    double aux = 0.0;
#pragma unroll
    for (int e = 0; e < En; e++) {
        double load = g_load_sums[e] / (double)Bn;
        aux += load * log(load * (double)En + 1e-9);
    }
    out_aux[0] = (float)(aux / log((double)En + 1e-9));
}

// ---------------- kernel: expert MLP — 256 threads, 64x64 warp tile ----------------
// 8 warps: warpM = wid&1 (2 x 64 rows), warpN = wid>>1 (4 x 64/32 cols).
// LDSM/MMA ratio cut 2.7x vs 16-warp config (probe: is HMMA rt 8 or 16?).
// Arena identical to R13 (160KB + pad).
#define ARENA_BYTES (163840 + 1024)
extern __shared__ char dsm[];

__global__ void __launch_bounds__(256, 1) expert_kernel(
    const float* __restrict__ b1g, const float* __restrict__ b2g)
{
    __shared__ int   toks[TMk];
    __shared__ int   tslot[TMk];
    __shared__ float twt[TMk];
    __shared__ float b1s[Hn];
    __shared__ float b2s[Dn];

    int e = blockIdx.y;
    int cnt = g_expert_count[e];
    int base = blockIdx.x * TMk;
    if (base >= cnt) return;

    int tid = threadIdx.x;
    int wid = tid >> 5, lane = tid & 31;

    uint32_t raw = smem_u32(dsm);
    uint32_t sb  = (raw + 1023u) & ~1023u;
    char* arena  = dsm + (sb - raw);

    if (tid < TMk) {
        int i = base + tid;
        if (i < cnt) {
            int v = g_expert_tok[e * Bn + i];
            toks[tid] = v & 0x3FFFFFFF; tslot[tid] = v >> 30;
            twt[tid] = g_expert_wt[e * Bn + i];
        } else { toks[tid] = 0; tslot[tid] = 0; twt[tid] = 0.0f; }
    }
    b1s[tid] = b1g[e * Hn + tid];
    for (int f = tid; f < Dn; f += 256) b2s[f] = b2g[e * Dn + f];
    __syncthreads();

    // ---- fragment address constants ----
    int g  = lane >> 3, r = lane & 7;
    int arow = (g & 1) * 8 + r, akoff = (g >> 1) * 16;
    int brow = (g >> 1) * 8 + r, bkoff = (g & 1) * 16;
    int warpM = wid & 1, warpN = wid >> 1;

    uint32_t aoff[4];
#pragma unroll
    for (int i = 0; i < 4; i++)
        aoff[i] = (uint32_t)(warpM * 64 + i * 16 + arow) * 128 + akoff;
    uint32_t boff1[4];
#pragma unroll
    for (int j2 = 0; j2 < 4; j2++)
        boff1[j2] = (uint32_t)(warpN * 64 + j2 * 16 + brow) * 128 + bkoff;

    // ---- staging tables (256 threads) ----
    const char* srcX[4]; uint32_t dstX[4];
#pragma unroll
    for (int p = 0; p < 4; p++) {
        int f = tid + p * 256, row = f >> 3, seg = f & 7;
        srcX[p] = (const char*)(g_Xh + (size_t)toks[row] * Dn) + seg * 16;
        dstX[p] = sw((uint32_t)row * 128 + seg * 16);
    }
    const __half* W1t = g_W1T + (size_t)e * Hn * Dn;
    const char* srcW[8]; uint32_t dstW[8];
#pragma unroll
    for (int p = 0; p < 8; p++) {
        int f = tid + p * 256, row = f >> 3, seg = f & 7;
        srcW[p] = (const char*)(W1t + (size_t)row * Dn) + seg * 16;
        dstW[p] = sw((uint32_t)row * 128 + seg * 16);
    }

    auto stage1 = [&](int ci, uint32_t bb) {
        uint32_t o = (uint32_t)ci * 128;
#pragma unroll
        for (int p = 0; p < 4; p++)
            cpa(bb + dstX[p], srcX[p] + o);
#pragma unroll
        for (int p = 0; p < 8; p++)
            cpa(bb + 16384 + dstW[p], srcW[p] + o);
    };

    // ================= GEMM1: C1[128x256] = X[128x1024] @ W1 (3-stage) =========
    float acc[4][8][4];
#pragma unroll
    for (int i = 0; i < 4; i++)
#pragma unroll
        for (int j = 0; j < 8; j++)
#pragma unroll
            for (int q = 0; q < 4; q++) acc[i][j][q] = 0.0f;

    stage1(0, sb);         cp_commit();
    stage1(1, sb + 49152); cp_commit();

    for (int ci = 0; ci < 16; ci++) {
        if (ci == 15) cp_wait0(); else cp_wait1();
        __syncthreads();
        if (ci + 2 < 16) { stage1(ci + 2, sb + 49152u * ((ci + 2) % 3)); cp_commit(); }

        uint32_t cb = sb + 49152u * (ci % 3);
        uint32_t xh = cb, wh = cb + 16384;
#pragma unroll
        for (int ks = 0; ks < 4; ks++) {
            uint32_t Ah[4][4];
#pragma unroll
            for (int i = 0; i < 4; i++)
                ldsm4(Ah[i], xh + sw(aoff[i] + ks * 32));
#pragma unroll
            for (int j2 = 0; j2 < 4; j2++) {
                uint32_t Bh[4];
                ldsm4(Bh, wh + sw(boff1[j2] + ks * 32));
#pragma unroll
                for (int i = 0; i < 4; i++) {
                    mma_h(acc[i][2 * j2],     Ah[i], Bh[0], Bh[1]);
                    mma_h(acc[i][2 * j2 + 1], Ah[i], Bh[2], Bh[3]);
                }
            }
        }
    }
    __syncthreads();   // all GEMM1 reads done before H/GEMM2 staging overwrites arena

    // ---- GEMM2 staging (merged kc-pairs: 32KB per stage, 3 buffers) ----
    const __half* W2t = g_W2T + (size_t)e * Dn * Hn;
    uint32_t srcO2[4], dst2[4];
#pragma unroll
    for (int p = 0; p < 4; p++) {
        int f = tid + p * 256, row = f >> 3, seg = f & 7;
        srcO2[p] = (uint32_t)row * 512 + seg * 16;
        dst2[p]  = sw((uint32_t)row * 128 + seg * 16);
    }
    auto stage2m = [&](int s, uint32_t bb) {
        int np = s >> 1;
#pragma unroll
        for (int sub = 0; sub < 2; sub++) {
            int kc = (s & 1) * 2 + sub;
            uint32_t o = (uint32_t)np * 65536 + (uint32_t)kc * 128;
#pragma unroll
            for (int p = 0; p < 4; p++)
                cpa(bb + sub * 16384 + dst2[p], (const char*)W2t + srcO2[p] + o);
        }
    };
    uint32_t b2base = sb + 65536;
    stage2m(0, b2base);          cp_commit();
    stage2m(1, b2base + 32768);  cp_commit();

    // ---- epilogue 1: bias + GELU -> fp16 H panels ----
    {
        int mb = warpM * 64, nb = warpN * 64;
#pragma unroll
        for (int i = 0; i < 4; i++)
#pragma unroll
            for (int j = 0; j < 8; j++) {
                int m0 = mb + i * 16 + (lane >> 2);
                int n0 = nb + j * 8 + (lane & 3) * 2;
                float bb0 = b1s[n0], bb1 = b1s[n0 + 1];
#pragma unroll
                for (int hr = 0; hr < 2; hr++) {
                    int m = m0 + hr * 8;
                    float v0 = gelu(acc[i][j][hr * 2]     + bb0);
                    float v1 = gelu(acc[i][j][hr * 2 + 1] + bb1);
                    uint32_t off = ((uint32_t)(n0 >> 6)) * 16384 + sw((uint32_t)m * 128 + (n0 & 63) * 2);
                    *(uint32_t*)(arena + off) = cvt2h(v0, v1);
                }
            }
    }

    // ================= GEMM2: out[128x1024] = H[128x256] @ W2 (16 merged stages) =====
    uint32_t boff2[2];
#pragma unroll
    for (int j2 = 0; j2 < 2; j2++)
        boff2[j2] = (uint32_t)(warpN * 32 + j2 * 16 + brow) * 128 + bkoff;

    float acc2[4][4][4];

    for (int s = 0; s < 16; s++) {
        int np = s >> 1;
        if (s == 15) cp_wait0(); else cp_wait1();
        __syncthreads();
        if (s + 2 < 16) { stage2m(s + 2, b2base + 32768u * ((s + 2) % 3)); cp_commit(); }

        if ((s & 1) == 0) {
#pragma unroll
            for (int i = 0; i < 4; i++)
#pragma unroll
                for (int j = 0; j < 4; j++)
#pragma unroll
                    for (int q = 0; q < 4; q++) acc2[i][j][q] = 0.0f;
        }

        uint32_t cbb = b2base + 32768u * (s % 3);
#pragma unroll
        for (int sub = 0; sub < 2; sub++) {
            int kc = (s & 1) * 2 + sub;
            uint32_t ah = sb + kc * 16384;
            uint32_t cb = cbb + sub * 16384;
#pragma unroll
            for (int ks = 0; ks < 4; ks++) {
                uint32_t Ah[4][4];
#pragma unroll
                for (int i = 0; i < 4; i++)
                    ldsm4(Ah[i], ah + sw(aoff[i] + ks * 32));
#pragma unroll
                for (int j2 = 0; j2 < 2; j2++) {
                    uint32_t Bh[4];
                    ldsm4(Bh, cb + sw(boff2[j2] + ks * 32));
#pragma unroll
                    for (int i = 0; i < 4; i++) {
                        mma_h(acc2[i][2 * j2],     Ah[i], Bh[0], Bh[1]);
                        mma_h(acc2[i][2 * j2 + 1], Ah[i], Bh[2], Bh[3]);
                    }
                }
            }
        }

        if (s & 1) {
            // epilogue 2: weighted bias-add -> per-slot fp16 buffer
            int mb = warpM * 64, nb = warpN * 32;
#pragma unroll
            for (int i = 0; i < 4; i++)
#pragma unroll
                for (int j = 0; j < 4; j++) {
                    int m0 = mb + i * 16 + (lane >> 2);
                    int n0 = np * 128 + nb + j * 8 + (lane & 3) * 2;
                    float bb0 = b2s[n0], bb1 = b2s[n0 + 1];
#pragma unroll
                    for (int hr = 0; hr < 2; hr++) {
                        int m = m0 + hr * 8;
                        if (base + m < cnt) {
                            int   tok  = toks[m];
                            float wgt  = twt[m];
                            float o0 = wgt * (acc2[i][j][hr * 2]     + bb0);
                            float o1 = wgt * (acc2[i][j][hr * 2 + 1] + bb1);
                            uint32_t* dst = (uint32_t*)((char*)g_bufh +
                                ((size_t)tslot[m] * BD + (size_t)tok * Dn + n0) * 2);
                            *dst = cvt2h(o0, o1);
                        }
                    }
                }
        }
    }
}

// ---------------- kernel: combine the two fp16 slots -> fp32 out ----------------
__global__ void combine_kernel(float* __restrict__ out) {
    size_t i = ((size_t)blockIdx.x * 512 + threadIdx.x) * 4;
    uint2 pa = *(const uint2*)((const char*)g_bufh + i * 2);
    uint2 pb = *(const uint2*)((const char*)g_bufh + ((size_t)BD + i) * 2);
    __half2 a0 = *(__half2*)&pa.x, a1 = *(__half2*)&pa.y;
    __half2 b0 = *(__half2*)&pb.x, b1 = *(__half2*)&pb.y;
    float2 fa0 = __half22float2(a0), fa1 = __half22float2(a1);
    float2 fb0 = __half22float2(b0), fb1 = __half22float2(b1);
    *(float4*)(out + i) = make_float4(fa0.x + fb0.x, fa0.y + fb0.y,
                                      fa1.x + fb1.x, fa1.y + fb1.y);
}

// ---------------- launch ----------------
extern "C" void kernel_launch(void* const* d_in, const int* in_sizes, int n_in,
                              void* d_out, int out_size) {
    const float* x  = (const float*)d_in[0];
    const float* Wr = (const float*)d_in[1];
    const float* br = (const float*)d_in[2];
    const float* W1 = (const float*)d_in[3];
    const float* b1 = (const float*)d_in[4];
    const float* W2 = (const float*)d_in[5];
    const float* b2 = (const float*)d_in[6];
    float* out = (float*)d_out;

    static cudaStream_t s_side = nullptr;
    static cudaEvent_t  ev_fork = nullptr, ev_join = nullptr,
                        ev_rt = nullptr, ev_aux = nullptr;
    if (!s_side) {
        cudaStreamCreateWithFlags(&s_side, cudaStreamNonBlocking);
        cudaEventCreateWithFlags(&ev_fork, cudaEventDisableTiming);
        cudaEventCreateWithFlags(&ev_join, cudaEventDisableTiming);
        cudaEventCreateWithFlags(&ev_rt,   cudaEventDisableTiming);
        cudaEventCreateWithFlags(&ev_aux,  cudaEventDisableTiming);
    }

    cudaFuncSetAttribute(expert_kernel,
                         cudaFuncAttributeMaxDynamicSharedMemorySize, ARENA_BYTES);

    prep_small<<<(Dn * En + 255) / 256, 256>>>(Wr);

    cudaEventRecord(ev_fork, 0);
    cudaStreamWaitEvent(s_side, ev_fork, 0);
    transpose_half_kernel<<<dim3(8, 32, En), dim3(32, 8), 0, s_side>>>(W1, Dn, Hn, 0);
    transpose_half_kernel<<<dim3(32, 8, En), dim3(32, 8), 0, s_side>>>(W2, Hn, Dn, 1);
    cudaEventRecord(ev_join, s_side);

    router_split_kernel<<<Bn / 16, 512>>>(x, br);
    cudaEventRecord(ev_rt, 0);

    if (out_size > BD) {
        cudaStreamWaitEvent(s_side, ev_rt, 0);
        aux_kernel<<<1, 1, 0, s_side>>>(out + (size_t)BD);
    }
    cudaEventRecord(ev_aux, s_side);

    cudaStreamWaitEvent(0, ev_join, 0);
    expert_kernel<<<dim3(Bn / TMk, En), 256, ARENA_BYTES>>>(b1, b2);
    combine_kernel<<<BD / 2048, 512>>>(out);
    cudaStreamWaitEvent(0, ev_aux, 0);
}

// round 15
// speedup vs baseline: 1.1252x; 1.1252x over previous
#include <cuda_runtime.h>
#include <cuda_fp16.h>
#include <math.h>
#include <stdint.h>

// Problem constants
#define Bn 16384
#define Dn 1024
#define En 6
#define Hn 256
#define TMk 128
#define BD 16777216

// ---------------- device scratch ----------------
__device__ double g_load_sums[En];
__device__ int    g_expert_count[En];
__device__ int    g_expert_tok[En * Bn];   // token | (slot<<30)
__device__ float  g_expert_wt[En * Bn];
__device__ float  g_WrT[En * Dn];          // router weight transposed [e][d]
__device__ __half g_Xh[Bn * Dn];           // x (fp16)
__device__ __half g_W1T[En * Hn * Dn];     // [e][h][d]  (K-major, n=h)
__device__ __half g_W2T[En * Dn * Hn];     // [e][d][h]  (K-major, n=d)
__device__ __half g_bufh[2u * Bn * Dn];    // per-slot weighted expert outputs (fp16)

// ---------------- helpers ----------------
__device__ __forceinline__ uint32_t smem_u32(const void* p) {
    uint32_t a;
    asm("{ .reg .u64 t; cvta.to.shared.u64 t, %1; cvt.u32.u64 %0, t; }" : "=r"(a) : "l"(p));
    return a;
}
__device__ __forceinline__ uint32_t sw(uint32_t o) { return o ^ ((o >> 3) & 0x70); }
__device__ __forceinline__ uint32_t cvt2h(float lo, float hi) {
    uint32_t r;
    asm("cvt.rn.f16x2.f32 %0, %1, %2;" : "=r"(r) : "f"(hi), "f"(lo));
    return r;
}
__device__ __forceinline__ void ldsm4(uint32_t* r, uint32_t a) {
    asm volatile("ldmatrix.sync.aligned.m8n8.x4.shared.b16 {%0,%1,%2,%3}, [%4];"
                 : "=r"(r[0]), "=r"(r[1]), "=r"(r[2]), "=r"(r[3]) : "r"(a));
}
__device__ __forceinline__ void mma_h(float* c, const uint32_t* a, uint32_t b0, uint32_t b1) {
    asm volatile(
        "mma.sync.aligned.m16n8k16.row.col.f32.f16.f16.f32 "
        "{%0,%1,%2,%3}, {%4,%5,%6,%7}, {%8,%9}, {%0,%1,%2,%3};"
        : "+f"(c[0]), "+f"(c[1]), "+f"(c[2]), "+f"(c[3])
        : "r"(a[0]), "r"(a[1]), "r"(a[2]), "r"(a[3]), "r"(b0), "r"(b1));
}
__device__ __forceinline__ void cpa(uint32_t dst, const void* src) {
    asm volatile("cp.async.cg.shared.global [%0], [%1], 16;" :: "r"(dst), "l"(src));
}
__device__ __forceinline__ void cp_commit() { asm volatile("cp.async.commit_group;"); }
__device__ __forceinline__ void cp_wait0()  { asm volatile("cp.async.wait_group 0;"); }
__device__ __forceinline__ void cp_wait1()  { asm volatile("cp.async.wait_group 1;"); }
__device__ __forceinline__ float gelu(float t) {
    return 0.5f * t * (1.0f + erff(t * 0.70710678118654752f));
}

// ---------------- kernel: zero counters + transpose Wr ----------------
__global__ void prep_small(const float* __restrict__ Wr) {
    int i = blockIdx.x * 256 + threadIdx.x;
    if (i < En) {
        g_load_sums[i] = 0.0;
        g_expert_count[i] = 0;
    }
    if (i < Dn * En) {
        int d = i / En, e = i % En;
        g_WrT[e * Dn + d] = Wr[i];
    }
}

// ---------------- kernel: weight transpose -> fp16 ----------------
__global__ void transpose_half_kernel(const float* __restrict__ src, int R, int C, int which) {
    __shared__ float tile[32][33];
    int e = blockIdx.z;
    int c0 = blockIdx.x * 32, r0 = blockIdx.y * 32;
    const float* s = src + (size_t)e * R * C;
    __half* d = (which == 0 ? g_W1T : g_W2T) + (size_t)e * R * C;
#pragma unroll
    for (int i = 0; i < 32; i += 8)
        tile[threadIdx.y + i][threadIdx.x] = s[(size_t)(r0 + threadIdx.y + i) * C + c0 + threadIdx.x];
    __syncthreads();
#pragma unroll
    for (int i = 0; i < 32; i += 8) {
        size_t o = (size_t)(c0 + threadIdx.y + i) * R + r0 + threadIdx.x;
        d[o] = __float2half_rn(tile[threadIdx.x][threadIdx.y + i]);
    }
}

// ---------------- kernel: fused router + x->fp16, block-aggregated atomics ----------------
// 256 threads = 8 warps = 8 tokens/block, grid Bn/8; 4 blocks/SM (32 warps).
__global__ void __launch_bounds__(256, 4) router_split_kernel(
    const float* __restrict__ x, const float* __restrict__ br)
{
    __shared__ float wsh[En * Dn];        // 24KB
    __shared__ float sm_p[8][En];
    __shared__ int   sm_pick[8][2];
    __shared__ float sm_w[8][2];

    int tid = threadIdx.x;
    int warp = tid >> 5, lane = tid & 31;
    for (int i = tid * 4; i < En * Dn; i += 1024)
        *(float4*)(wsh + i) = *(const float4*)(g_WrT + i);
    __syncthreads();

    int t = blockIdx.x * 8 + warp;
    {
        const float* xr = x + (size_t)t * Dn;
        char* dh = (char*)g_Xh + (size_t)t * Dn * 2;

        float acc[En];
#pragma unroll
        for (int e = 0; e < En; e++) acc[e] = 0.0f;

#pragma unroll
        for (int half = 0; half < 2; half++) {
            float4 v[4];
#pragma unroll
            for (int jj = 0; jj < 4; jj++)
                v[jj] = *(const float4*)(xr + (lane + 32 * (half * 4 + jj)) * 4);
#pragma unroll
            for (int jj = 0; jj < 4; jj++) {
                int d0 = (lane + 32 * (half * 4 + jj)) * 4;
#pragma unroll
                for (int e = 0; e < En; e++) {
                    float4 w = *(const float4*)(wsh + e * Dn + d0);
                    acc[e] = fmaf(v[jj].x, w.x, acc[e]);
                    acc[e] = fmaf(v[jj].y, w.y, acc[e]);
                    acc[e] = fmaf(v[jj].z, w.z, acc[e]);
                    acc[e] = fmaf(v[jj].w, w.w, acc[e]);
                }
                *(uint2*)(dh + d0 * 2) = make_uint2(cvt2h(v[jj].x, v[jj].y),
                                                    cvt2h(v[jj].z, v[jj].w));
            }
        }
#pragma unroll
        for (int off = 16; off > 0; off >>= 1)
#pragma unroll
            for (int e = 0; e < En; e++)
                acc[e] += __shfl_xor_sync(0xffffffffu, acc[e], off);

        if (lane == 0) {
            float p[En];
            float m = -1e30f;
#pragma unroll
            for (int e = 0; e < En; e++) { p[e] = acc[e] + br[e]; m = fmaxf(m, p[e]); }
            float s = 0.0f;
#pragma unroll
            for (int e = 0; e < En; e++) { p[e] = expf(p[e] - m); s += p[e]; }
            float inv = 1.0f / s;
#pragma unroll
            for (int e = 0; e < En; e++) {
                p[e] = 0.9f * p[e] * inv + (0.1f / 6.0f);
                sm_p[warp][e] = p[e];
            }
            int i0 = 0;
#pragma unroll
            for (int e = 1; e < En; e++) if (p[e] > p[i0]) i0 = e;
            int i1 = (i0 == 0) ? 1 : 0;
#pragma unroll
            for (int e = 0; e < En; e++) if (e != i0 && p[e] > p[i1]) i1 = e;
            sm_pick[warp][0] = i0; sm_pick[warp][1] = i1;
            sm_w[warp][0] = p[i0]; sm_w[warp][1] = p[i1];
        }
    }
    __syncthreads();

    if (tid < En) {
        int e = tid;
        double s = 0.0;
        int cnt = 0;
#pragma unroll
        for (int w = 0; w < 8; w++) {
            s += (double)sm_p[w][e];
            cnt += (sm_pick[w][0] == e) + (sm_pick[w][1] == e);
        }
        atomicAdd(&g_load_sums[e], s);
        int base = atomicAdd(&g_expert_count[e], cnt);
#pragma unroll
        for (int w = 0; w < 8; w++) {
            int tt = blockIdx.x * 8 + w;
            if (sm_pick[w][0] == e) {
                g_expert_tok[e * Bn + base] = tt;
                g_expert_wt[e * Bn + base] = sm_w[w][0];
                base++;
            }
            if (sm_pick[w][1] == e) {
                g_expert_tok[e * Bn + base] = tt | (1 << 30);
                g_expert_wt[e * Bn + base] = sm_w[w][1];
                base++;
            }
        }
    }
}

// ---------------- kernel: aux scalar ----------------
__global__ void aux_kernel(float* __restrict__ out_aux) {
    double aux = 0.0;
#pragma unroll
    for (int e = 0; e < En; e++) {
        double load = g_load_sums[e] / (double)Bn;
        aux += load * log(load * (double)En + 1e-9);
    }
    out_aux[0] = (float)(aux / log((double)En + 1e-9));
}

// ---------------- kernel: expert MLP (R13 config: 512 thr, 16 warps, 32x64 tile) ----------------
// Arena (160KB + pad):
//  GEMM1 (3-stage): B(c) = sb + 49152*(c%3): Xh+0(16K) W+16384(32K)
//  H panels (post-GEMM1): 4 x 16K at sb+0..65535
//  GEMM2 (3 x 32K merged-kc stages): C(s) = sb + 65536 + 32768*(s%3)
#define ARENA_BYTES (163840 + 1024)
extern __shared__ char dsm[];

__global__ void __launch_bounds__(512, 1) expert_kernel(
    const float* __restrict__ b1g, const float* __restrict__ b2g)
{
    __shared__ int   toks[TMk];
    __shared__ int   tslot[TMk];
    __shared__ float twt[TMk];
    __shared__ float b1s[Hn];
    __shared__ float b2s[Dn];

    int e = blockIdx.y;
    int cnt = g_expert_count[e];
    int base = blockIdx.x * TMk;
    if (base >= cnt) return;

    int tid = threadIdx.x;
    int wid = tid >> 5, lane = tid & 31;

    uint32_t raw = smem_u32(dsm);
    uint32_t sb  = (raw + 1023u) & ~1023u;
    char* arena  = dsm + (sb - raw);

    if (tid < TMk) {
        int i = base + tid;
        if (i < cnt) {
            int v = g_expert_tok[e * Bn + i];
            toks[tid] = v & 0x3FFFFFFF; tslot[tid] = v >> 30;
            twt[tid] = g_expert_wt[e * Bn + i];
        } else { toks[tid] = 0; tslot[tid] = 0; twt[tid] = 0.0f; }
    }
    if (tid < Hn) b1s[tid] = b1g[e * Hn + tid];
    for (int f = tid; f < Dn; f += 512) b2s[f] = b2g[e * Dn + f];
    __syncthreads();

    // ---- fragment address constants ----
    int g  = lane >> 3, r = lane & 7;
    int arow = (g & 1) * 8 + r, akoff = (g >> 1) * 16;
    int brow = (g >> 1) * 8 + r, bkoff = (g & 1) * 16;
    int warpM = wid & 3, warpN = wid >> 2;

    uint32_t aoff[2];
    aoff[0] = (uint32_t)(warpM * 32 + arow) * 128 + akoff;
    aoff[1] = aoff[0] + 16 * 128;
    uint32_t boff1[4];
#pragma unroll
    for (int j2 = 0; j2 < 4; j2++)
        boff1[j2] = (uint32_t)(warpN * 64 + j2 * 16 + brow) * 128 + bkoff;

    // ---- staging tables ----
    const char* srcX[2]; uint32_t dstX[2];
#pragma unroll
    for (int p = 0; p < 2; p++) {
        int f = tid + p * 512, row = f >> 3, seg = f & 7;
        srcX[p] = (const char*)(g_Xh + (size_t)toks[row] * Dn) + seg * 16;
        dstX[p] = sw((uint32_t)row * 128 + seg * 16);
    }
    const __half* W1t = g_W1T + (size_t)e * Hn * Dn;
    const char* srcW[4]; uint32_t dstW[4];
#pragma unroll
    for (int p = 0; p < 4; p++) {
        int f = tid + p * 512, row = f >> 3, seg = f & 7;
        srcW[p] = (const char*)(W1t + (size_t)row * Dn) + seg * 16;
        dstW[p] = sw((uint32_t)row * 128 + seg * 16);
    }

    auto stage1 = [&](int ci, uint32_t bb) {
        uint32_t o = (uint32_t)ci * 128;
#pragma unroll
        for (int p = 0; p < 2; p++)
            cpa(bb + dstX[p], srcX[p] + o);
#pragma unroll
        for (int p = 0; p < 4; p++)
            cpa(bb + 16384 + dstW[p], srcW[p] + o);
    };

    // ================= GEMM1: C1[128x256] = X[128x1024] @ W1 (3-stage) =========
    float acc[2][8][4];
#pragma unroll
    for (int i = 0; i < 2; i++)
#pragma unroll
        for (int j = 0; j < 8; j++)
#pragma unroll
            for (int q = 0; q < 4; q++) acc[i][j][q] = 0.0f;

    stage1(0, sb);         cp_commit();
    stage1(1, sb + 49152); cp_commit();

    for (int ci = 0; ci < 16; ci++) {
        if (ci == 15) cp_wait0(); else cp_wait1();
        __syncthreads();
        if (ci + 2 < 16) { stage1(ci + 2, sb + 49152u * ((ci + 2) % 3)); cp_commit(); }

        uint32_t cb = sb + 49152u * (ci % 3);
        uint32_t xh = cb, wh = cb + 16384;
#pragma unroll
        for (int ks = 0; ks < 4; ks++) {
            uint32_t Ah[2][4];
#pragma unroll
            for (int i = 0; i < 2; i++)
                ldsm4(Ah[i], xh + sw(aoff[i] + ks * 32));
#pragma unroll
            for (int j2 = 0; j2 < 4; j2++) {
                uint32_t Bh[4];
                ldsm4(Bh, wh + sw(boff1[j2] + ks * 32));
#pragma unroll
                for (int i = 0; i < 2; i++) {
                    mma_h(acc[i][2 * j2],     Ah[i], Bh[0], Bh[1]);
                    mma_h(acc[i][2 * j2 + 1], Ah[i], Bh[2], Bh[3]);
                }
            }
        }
    }
    __syncthreads();   // all GEMM1 reads done before H/GEMM2 staging overwrites arena

    // ---- GEMM2 staging (merged kc-pairs: 32KB per stage, 3 buffers) ----
    const __half* W2t = g_W2T + (size_t)e * Dn * Hn;
    uint32_t srcO2[2], dst2[2];
#pragma unroll
    for (int p = 0; p < 2; p++) {
        int f = tid + p * 512, row = f >> 3, seg = f & 7;
        srcO2[p] = (uint32_t)row * 512 + seg * 16;
        dst2[p]  = sw((uint32_t)row * 128 + seg * 16);
    }
    auto stage2m = [&](int s, uint32_t bb) {
        int np = s >> 1;
#pragma unroll
        for (int sub = 0; sub < 2; sub++) {
            int kc = (s & 1) * 2 + sub;
            uint32_t o = (uint32_t)np * 65536 + (uint32_t)kc * 128;
#pragma unroll
            for (int p = 0; p < 2; p++)
                cpa(bb + sub * 16384 + dst2[p], (const char*)W2t + srcO2[p] + o);
        }
    };
    uint32_t b2base = sb + 65536;
    stage2m(0, b2base);          cp_commit();
    stage2m(1, b2base + 32768);  cp_commit();

    // ---- epilogue 1: bias + GELU -> fp16 H panels ----
    {
        int mb = warpM * 32, nb = warpN * 64;
#pragma unroll
        for (int i = 0; i < 2; i++)
#pragma unroll
            for (int j = 0; j < 8; j++) {
                int m0 = mb + i * 16 + (lane >> 2);
                int n0 = nb + j * 8 + (lane & 3) * 2;
                float bb0 = b1s[n0], bb1 = b1s[n0 + 1];
#pragma unroll
                for (int hr = 0; hr < 2; hr++) {
                    int m = m0 + hr * 8;
                    float v0 = gelu(acc[i][j][hr * 2]     + bb0);
                    float v1 = gelu(acc[i][j][hr * 2 + 1] + bb1);
                    uint32_t off = ((uint32_t)(n0 >> 6)) * 16384 + sw((uint32_t)m * 128 + (n0 & 63) * 2);
                    *(uint32_t*)(arena + off) = cvt2h(v0, v1);
                }
            }
    }

    // ================= GEMM2: out[128x1024] = H[128x256] @ W2 (16 merged stages) =====
    uint32_t boff2[2];
#pragma unroll
    for (int j2 = 0; j2 < 2; j2++)
        boff2[j2] = (uint32_t)(warpN * 32 + j2 * 16 + brow) * 128 + bkoff;

    float acc2[2][4][4];

    for (int s = 0; s < 16; s++) {
        int np = s >> 1;
        if (s == 15) cp_wait0(); else cp_wait1();
        __syncthreads();
        if (s + 2 < 16) { stage2m(s + 2, b2base + 32768u * ((s + 2) % 3)); cp_commit(); }

        if ((s & 1) == 0) {
#pragma unroll
            for (int i = 0; i < 2; i++)
#pragma unroll
                for (int j = 0; j < 4; j++)
#pragma unroll
                    for (int q = 0; q < 4; q++) acc2[i][j][q] = 0.0f;
        }

        uint32_t cbb = b2base + 32768u * (s % 3);
#pragma unroll
        for (int sub = 0; sub < 2; sub++) {
            int kc = (s & 1) * 2 + sub;
            uint32_t ah = sb + kc * 16384;
            uint32_t cb = cbb + sub * 16384;
#pragma unroll
            for (int ks = 0; ks < 4; ks++) {
                uint32_t Ah[2][4];
#pragma unroll
                for (int i = 0; i < 2; i++)
                    ldsm4(Ah[i], ah + sw(aoff[i] + ks * 32));
#pragma unroll
                for (int j2 = 0; j2 < 2; j2++) {
                    uint32_t Bh[4];
                    ldsm4(Bh, cb + sw(boff2[j2] + ks * 32));
#pragma unroll
                    for (int i = 0; i < 2; i++) {
                        mma_h(acc2[i][2 * j2],     Ah[i], Bh[0], Bh[1]);
                        mma_h(acc2[i][2 * j2 + 1], Ah[i], Bh[2], Bh[3]);
                    }
                }
            }
        }

        if (s & 1) {
            // epilogue 2: weighted bias-add -> per-slot fp16 buffer
            int mb = warpM * 32, nb = warpN * 32;
#pragma unroll
            for (int i = 0; i < 2; i++)
#pragma unroll
                for (int j = 0; j < 4; j++) {
                    int m0 = mb + i * 16 + (lane >> 2);
                    int n0 = np * 128 + nb + j * 8 + (lane & 3) * 2;
                    float bb0 = b2s[n0], bb1 = b2s[n0 + 1];
#pragma unroll
                    for (int hr = 0; hr < 2; hr++) {
                        int m = m0 + hr * 8;
                        if (base + m < cnt) {
                            int   tok  = toks[m];
                            float wgt  = twt[m];
                            float o0 = wgt * (acc2[i][j][hr * 2]     + bb0);
                            float o1 = wgt * (acc2[i][j][hr * 2 + 1] + bb1);
                            uint32_t* dst = (uint32_t*)((char*)g_bufh +
                                ((size_t)tslot[m] * BD + (size_t)tok * Dn + n0) * 2);
                            *dst = cvt2h(o0, o1);
                        }
                    }
                }
        }
    }
}

// ---------------- kernel: combine the two fp16 slots -> fp32 out ----------------
__global__ void combine_kernel(float* __restrict__ out) {
    size_t i = ((size_t)blockIdx.x * 512 + threadIdx.x) * 4;
    uint2 pa = *(const uint2*)((const char*)g_bufh + i * 2);
    uint2 pb = *(const uint2*)((const char*)g_bufh + ((size_t)BD + i) * 2);
    __half2 a0 = *(__half2*)&pa.x, a1 = *(__half2*)&pa.y;
    __half2 b0 = *(__half2*)&pb.x, b1 = *(__half2*)&pb.y;
    float2 fa0 = __half22float2(a0), fa1 = __half22float2(a1);
    float2 fb0 = __half22float2(b0), fb1 = __half22float2(b1);
    *(float4*)(out + i) = make_float4(fa0.x + fb0.x, fa0.y + fb0.y,
                                      fa1.x + fb1.x, fa1.y + fb1.y);
}

// ---------------- launch ----------------
extern "C" void kernel_launch(void* const* d_in, const int* in_sizes, int n_in,
                              void* d_out, int out_size) {
    const float* x  = (const float*)d_in[0];
    const float* Wr = (const float*)d_in[1];
    const float* br = (const float*)d_in[2];
    const float* W1 = (const float*)d_in[3];
    const float* b1 = (const float*)d_in[4];
    const float* W2 = (const float*)d_in[5];
    const float* b2 = (const float*)d_in[6];
    float* out = (float*)d_out;

    static cudaStream_t s_side = nullptr;
    static cudaEvent_t  ev_fork = nullptr, ev_join = nullptr,
                        ev_rt = nullptr, ev_aux = nullptr;
    if (!s_side) {
        cudaStreamCreateWithFlags(&s_side, cudaStreamNonBlocking);
        cudaEventCreateWithFlags(&ev_fork, cudaEventDisableTiming);
        cudaEventCreateWithFlags(&ev_join, cudaEventDisableTiming);
        cudaEventCreateWithFlags(&ev_rt,   cudaEventDisableTiming);
        cudaEventCreateWithFlags(&ev_aux,  cudaEventDisableTiming);
    }

    cudaFuncSetAttribute(expert_kernel,
                         cudaFuncAttributeMaxDynamicSharedMemorySize, ARENA_BYTES);

    prep_small<<<(Dn * En + 255) / 256, 256>>>(Wr);

    cudaEventRecord(ev_fork, 0);
    cudaStreamWaitEvent(s_side, ev_fork, 0);
    transpose_half_kernel<<<dim3(8, 32, En), dim3(32, 8), 0, s_side>>>(W1, Dn, Hn, 0);
    transpose_half_kernel<<<dim3(32, 8, En), dim3(32, 8), 0, s_side>>>(W2, Hn, Dn, 1);
    cudaEventRecord(ev_join, s_side);

    router_split_kernel<<<Bn / 8, 256>>>(x, br);
    cudaEventRecord(ev_rt, 0);

    if (out_size > BD) {
        cudaStreamWaitEvent(s_side, ev_rt, 0);
        aux_kernel<<<1, 1, 0, s_side>>>(out + (size_t)BD);
    }
    cudaEventRecord(ev_aux, s_side);

    cudaStreamWaitEvent(0, ev_join, 0);
    expert_kernel<<<dim3(Bn / TMk, En), 512, ARENA_BYTES>>>(b1, b2);
    combine_kernel<<<BD / 2048, 512>>>(out);
    cudaStreamWaitEvent(0, ev_aux, 0);
}

// round 16
// speedup vs baseline: 1.1259x; 1.0007x over previous
#include <cuda_runtime.h>
#include <cuda_fp16.h>
#include <math.h>
#include <stdint.h>

// Problem constants
#define Bn 16384
#define Dn 1024
#define En 6
#define Hn 256
#define TMk 128
#define BD 16777216

// ---------------- device scratch ----------------
__device__ double g_load_sums[En];
__device__ int    g_expert_count[En];
__device__ int    g_expert_tok[En * Bn];   // token | (slot<<30)
__device__ float  g_expert_wt[En * Bn];
__device__ float  g_WrT[En * Dn];          // router weight transposed [e][d]
__device__ __half g_Xh[Bn * Dn];           // x (fp16)
__device__ __half g_W1T[En * Hn * Dn];     // [e][h][d]  (K-major, n=h)
__device__ __half g_W2T[En * Dn * Hn];     // [e][d][h]  (K-major, n=d)
__device__ __half g_bufh[2u * Bn * Dn];    // per-slot weighted expert outputs (fp16)

// ---------------- helpers ----------------
__device__ __forceinline__ uint32_t smem_u32(const void* p) {
    uint32_t a;
    asm("{ .reg .u64 t; cvta.to.shared.u64 t, %1; cvt.u32.u64 %0, t; }" : "=r"(a) : "l"(p));
    return a;
}
__device__ __forceinline__ uint32_t sw(uint32_t o) { return o ^ ((o >> 3) & 0x70); }
__device__ __forceinline__ uint32_t cvt2h(float lo, float hi) {
    uint32_t r;
    asm("cvt.rn.f16x2.f32 %0, %1, %2;" : "=r"(r) : "f"(hi), "f"(lo));
    return r;
}
__device__ __forceinline__ void ldsm4(uint32_t* r, uint32_t a) {
    asm volatile("ldmatrix.sync.aligned.m8n8.x4.shared.b16 {%0,%1,%2,%3}, [%4];"
                 : "=r"(r[0]), "=r"(r[1]), "=r"(r[2]), "=r"(r[3]) : "r"(a));
}
__device__ __forceinline__ void mma_h(float* c, const uint32_t* a, uint32_t b0, uint32_t b1) {
    asm volatile(
        "mma.sync.aligned.m16n8k16.row.col.f32.f16.f16.f32 "
        "{%0,%1,%2,%3}, {%4,%5,%6,%7}, {%8,%9}, {%0,%1,%2,%3};"
        : "+f"(c[0]), "+f"(c[1]), "+f"(c[2]), "+f"(c[3])
        : "r"(a[0]), "r"(a[1]), "r"(a[2]), "r"(a[3]), "r"(b0), "r"(b1));
}
__device__ __forceinline__ void cpa(uint32_t dst, const void* src) {
    asm volatile("cp.async.cg.shared.global [%0], [%1], 16;" :: "r"(dst), "l"(src));
}
__device__ __forceinline__ void cp_commit() { asm volatile("cp.async.commit_group;"); }
__device__ __forceinline__ void cp_wait0()  { asm volatile("cp.async.wait_group 0;"); }
__device__ __forceinline__ void cp_wait1()  { asm volatile("cp.async.wait_group 1;"); }
__device__ __forceinline__ float gelu(float t) {
    return 0.5f * t * (1.0f + erff(t * 0.70710678118654752f));
}

// ---------------- kernel: zero counters + transpose Wr ----------------
__global__ void prep_small(const float* __restrict__ Wr) {
    int i = blockIdx.x * 256 + threadIdx.x;
    if (i < En) {
        g_load_sums[i] = 0.0;
        g_expert_count[i] = 0;
    }
    if (i < Dn * En) {
        int d = i / En, e = i % En;
        g_WrT[e * Dn + d] = Wr[i];
    }
}

// ---------------- kernel: weight transpose -> fp16 ----------------
__global__ void transpose_half_kernel(const float* __restrict__ src, int R, int C, int which) {
    __shared__ float tile[32][33];
    int e = blockIdx.z;
    int c0 = blockIdx.x * 32, r0 = blockIdx.y * 32;
    const float* s = src + (size_t)e * R * C;
    __half* d = (which == 0 ? g_W1T : g_W2T) + (size_t)e * R * C;
#pragma unroll
    for (int i = 0; i < 32; i += 8)
        tile[threadIdx.y + i][threadIdx.x] = s[(size_t)(r0 + threadIdx.y + i) * C + c0 + threadIdx.x];
    __syncthreads();
#pragma unroll
    for (int i = 0; i < 32; i += 8) {
        size_t o = (size_t)(c0 + threadIdx.y + i) * R + r0 + threadIdx.x;
        d[o] = __float2half_rn(tile[threadIdx.x][threadIdx.y + i]);
    }
}

// ---------------- kernel: fused router + x->fp16, block-aggregated atomics ----------------
// 256 threads = 8 warps = 8 tokens/block, grid Bn/8; 4 blocks/SM (32 warps).
__global__ void __launch_bounds__(256, 4) router_split_kernel(
    const float* __restrict__ x, const float* __restrict__ br)
{
    __shared__ float wsh[En * Dn];        // 24KB
    __shared__ float sm_p[8][En];
    __shared__ int   sm_pick[8][2];
    __shared__ float sm_w[8][2];

    int tid = threadIdx.x;
    int warp = tid >> 5, lane = tid & 31;
    for (int i = tid * 4; i < En * Dn; i += 1024)
        *(float4*)(wsh + i) = *(const float4*)(g_WrT + i);
    __syncthreads();

    int t = blockIdx.x * 8 + warp;
    {
        const float* xr = x + (size_t)t * Dn;
        char* dh = (char*)g_Xh + (size_t)t * Dn * 2;

        float acc[En];
#pragma unroll
        for (int e = 0; e < En; e++) acc[e] = 0.0f;

#pragma unroll
        for (int half = 0; half < 2; half++) {
            float4 v[4];
#pragma unroll
            for (int jj = 0; jj < 4; jj++)
                v[jj] = *(const float4*)(xr + (lane + 32 * (half * 4 + jj)) * 4);
#pragma unroll
            for (int jj = 0; jj < 4; jj++) {
                int d0 = (lane + 32 * (half * 4 + jj)) * 4;
#pragma unroll
                for (int e = 0; e < En; e++) {
                    float4 w = *(const float4*)(wsh + e * Dn + d0);
                    acc[e] = fmaf(v[jj].x, w.x, acc[e]);
                    acc[e] = fmaf(v[jj].y, w.y, acc[e]);
                    acc[e] = fmaf(v[jj].z, w.z, acc[e]);
                    acc[e] = fmaf(v[jj].w, w.w, acc[e]);
                }
                *(uint2*)(dh + d0 * 2) = make_uint2(cvt2h(v[jj].x, v[jj].y),
                                                    cvt2h(v[jj].z, v[jj].w));
            }
        }
#pragma unroll
        for (int off = 16; off > 0; off >>= 1)
#pragma unroll
            for (int e = 0; e < En; e++)
                acc[e] += __shfl_xor_sync(0xffffffffu, acc[e], off);

        if (lane == 0) {
            float p[En];
            float m = -1e30f;
#pragma unroll
            for (int e = 0; e < En; e++) { p[e] = acc[e] + br[e]; m = fmaxf(m, p[e]); }
            float s = 0.0f;
#pragma unroll
            for (int e = 0; e < En; e++) { p[e] = expf(p[e] - m); s += p[e]; }
            float inv = 1.0f / s;
#pragma unroll
            for (int e = 0; e < En; e++) {
                p[e] = 0.9f * p[e] * inv + (0.1f / 6.0f);
                sm_p[warp][e] = p[e];
            }
            int i0 = 0;
#pragma unroll
            for (int e = 1; e < En; e++) if (p[e] > p[i0]) i0 = e;
            int i1 = (i0 == 0) ? 1 : 0;
#pragma unroll
            for (int e = 0; e < En; e++) if (e != i0 && p[e] > p[i1]) i1 = e;
            sm_pick[warp][0] = i0; sm_pick[warp][1] = i1;
            sm_w[warp][0] = p[i0]; sm_w[warp][1] = p[i1];
        }
    }
    __syncthreads();

    if (tid < En) {
        int e = tid;
        double s = 0.0;
        int cnt = 0;
#pragma unroll
        for (int w = 0; w < 8; w++) {
            s += (double)sm_p[w][e];
            cnt += (sm_pick[w][0] == e) + (sm_pick[w][1] == e);
        }
        atomicAdd(&g_load_sums[e], s);
        int base = atomicAdd(&g_expert_count[e], cnt);
#pragma unroll
        for (int w = 0; w < 8; w++) {
            int tt = blockIdx.x * 8 + w;
            if (sm_pick[w][0] == e) {
                g_expert_tok[e * Bn + base] = tt;
                g_expert_wt[e * Bn + base] = sm_w[w][0];
                base++;
            }
            if (sm_pick[w][1] == e) {
                g_expert_tok[e * Bn + base] = tt | (1 << 30);
                g_expert_wt[e * Bn + base] = sm_w[w][1];
                base++;
            }
        }
    }
}

// ---------------- kernel: aux scalar ----------------
__global__ void aux_kernel(float* __restrict__ out_aux) {
    double aux = 0.0;
#pragma unroll
    for (int e = 0; e < En; e++) {
        double load = g_load_sums[e] / (double)Bn;
        aux += load * log(load * (double)En + 1e-9);
    }
    out_aux[0] = (float)(aux / log((double)En + 1e-9));
}

// ---------------- kernel: expert MLP (R13 config: 512 thr, 16 warps, 32x64 tile) ----------------
// Arena (160KB + pad):
//  GEMM1 (3-stage): B(c) = sb + 49152*(c%3): Xh+0(16K) W+16384(32K)
//  H panels (post-GEMM1): 4 x 16K at sb+0..65535
//  GEMM2 (3 x 32K merged-kc stages): C(s) = sb + 65536 + 32768*(s%3)
#define ARENA_BYTES (163840 + 1024)
extern __shared__ char dsm[];

__global__ void __launch_bounds__(512, 1) expert_kernel(
    const float* __restrict__ b1g, const float* __restrict__ b2g)
{
    __shared__ int   toks[TMk];
    __shared__ int   tslot[TMk];
    __shared__ float twt[TMk];
    __shared__ float b1s[Hn];
    __shared__ float b2s[Dn];

    int e = blockIdx.y;
    int cnt = g_expert_count[e];
    int base = blockIdx.x * TMk;
    if (base >= cnt) return;

    int tid = threadIdx.x;
    int wid = tid >> 5, lane = tid & 31;

    uint32_t raw = smem_u32(dsm);
    uint32_t sb  = (raw + 1023u) & ~1023u;
    char* arena  = dsm + (sb - raw);

    if (tid < TMk) {
        int i = base + tid;
        if (i < cnt) {
            int v = g_expert_tok[e * Bn + i];
            toks[tid] = v & 0x3FFFFFFF; tslot[tid] = v >> 30;
            twt[tid] = g_expert_wt[e * Bn + i];
        } else { toks[tid] = 0; tslot[tid] = 0; twt[tid] = 0.0f; }
    }
    if (tid < Hn) b1s[tid] = b1g[e * Hn + tid];
    for (int f = tid; f < Dn; f += 512) b2s[f] = b2g[e * Dn + f];
    __syncthreads();

    // ---- fragment address constants ----
    int g  = lane >> 3, r = lane & 7;
    int arow = (g & 1) * 8 + r, akoff = (g >> 1) * 16;
    int brow = (g >> 1) * 8 + r, bkoff = (g & 1) * 16;
    int warpM = wid & 3, warpN = wid >> 2;

    uint32_t aoff[2];
    aoff[0] = (uint32_t)(warpM * 32 + arow) * 128 + akoff;
    aoff[1] = aoff[0] + 16 * 128;
    uint32_t boff1[4];
#pragma unroll
    for (int j2 = 0; j2 < 4; j2++)
        boff1[j2] = (uint32_t)(warpN * 64 + j2 * 16 + brow) * 128 + bkoff;

    // ---- staging tables ----
    const char* srcX[2]; uint32_t dstX[2];
#pragma unroll
    for (int p = 0; p < 2; p++) {
        int f = tid + p * 512, row = f >> 3, seg = f & 7;
        srcX[p] = (const char*)(g_Xh + (size_t)toks[row] * Dn) + seg * 16;
        dstX[p] = sw((uint32_t)row * 128 + seg * 16);
    }
    const __half* W1t = g_W1T + (size_t)e * Hn * Dn;
    const char* srcW[4]; uint32_t dstW[4];
#pragma unroll
    for (int p = 0; p < 4; p++) {
        int f = tid + p * 512, row = f >> 3, seg = f & 7;
        srcW[p] = (const char*)(W1t + (size_t)row * Dn) + seg * 16;
        dstW[p] = sw((uint32_t)row * 128 + seg * 16);
    }

    auto stage1 = [&](int ci, uint32_t bb) {
        uint32_t o = (uint32_t)ci * 128;
#pragma unroll
        for (int p = 0; p < 2; p++)
            cpa(bb + dstX[p], srcX[p] + o);
#pragma unroll
        for (int p = 0; p < 4; p++)
            cpa(bb + 16384 + dstW[p], srcW[p] + o);
    };

    // ================= GEMM1: C1[128x256] = X[128x1024] @ W1 (3-stage) =========
    float acc[2][8][4];
#pragma unroll
    for (int i = 0; i < 2; i++)
#pragma unroll
        for (int j = 0; j < 8; j++)
#pragma unroll
            for (int q = 0; q < 4; q++) acc[i][j][q] = 0.0f;

    stage1(0, sb);         cp_commit();
    stage1(1, sb + 49152); cp_commit();

    for (int ci = 0; ci < 16; ci++) {
        if (ci == 15) cp_wait0(); else cp_wait1();
        __syncthreads();
        if (ci + 2 < 16) { stage1(ci + 2, sb + 49152u * ((ci + 2) % 3)); cp_commit(); }

        uint32_t cb = sb + 49152u * (ci % 3);
        uint32_t xh = cb, wh = cb + 16384;
#pragma unroll
        for (int ks = 0; ks < 4; ks++) {
            uint32_t Ah[2][4];
#pragma unroll
            for (int i = 0; i < 2; i++)
                ldsm4(Ah[i], xh + sw(aoff[i] + ks * 32));
#pragma unroll
            for (int j2 = 0; j2 < 4; j2++) {
                uint32_t Bh[4];
                ldsm4(Bh, wh + sw(boff1[j2] + ks * 32));
#pragma unroll
                for (int i = 0; i < 2; i++) {
                    mma_h(acc[i][2 * j2],     Ah[i], Bh[0], Bh[1]);
                    mma_h(acc[i][2 * j2 + 1], Ah[i], Bh[2], Bh[3]);
                }
            }
        }
    }
    __syncthreads();   // all GEMM1 reads done before H/GEMM2 staging overwrites arena

    // ---- GEMM2 staging (merged kc-pairs: 32KB per stage, 3 buffers) ----
    const __half* W2t = g_W2T + (size_t)e * Dn * Hn;
    uint32_t srcO2[2], dst2[2];
#pragma unroll
    for (int p = 0; p < 2; p++) {
        int f = tid + p * 512, row = f >> 3, seg = f & 7;
        srcO2[p] = (uint32_t)row * 512 + seg * 16;
        dst2[p]  = sw((uint32_t)row * 128 + seg * 16);
    }
    auto stage2m = [&](int s, uint32_t bb) {
        int np = s >> 1;
#pragma unroll
        for (int sub = 0; sub < 2; sub++) {
            int kc = (s & 1) * 2 + sub;
            uint32_t o = (uint32_t)np * 65536 + (uint32_t)kc * 128;
#pragma unroll
            for (int p = 0; p < 2; p++)
                cpa(bb + sub * 16384 + dst2[p], (const char*)W2t + srcO2[p] + o);
        }
    };
    uint32_t b2base = sb + 65536;
    stage2m(0, b2base);          cp_commit();
    stage2m(1, b2base + 32768);  cp_commit();

    // ---- epilogue 1: bias + GELU -> fp16 H panels ----
    {
        int mb = warpM * 32, nb = warpN * 64;
#pragma unroll
        for (int i = 0; i < 2; i++)
#pragma unroll
            for (int j = 0; j < 8; j++) {
                int m0 = mb + i * 16 + (lane >> 2);
                int n0 = nb + j * 8 + (lane & 3) * 2;
                float bb0 = b1s[n0], bb1 = b1s[n0 + 1];
#pragma unroll
                for (int hr = 0; hr < 2; hr++) {
                    int m = m0 + hr * 8;
                    float v0 = gelu(acc[i][j][hr * 2]     + bb0);
                    float v1 = gelu(acc[i][j][hr * 2 + 1] + bb1);
                    uint32_t off = ((uint32_t)(n0 >> 6)) * 16384 + sw((uint32_t)m * 128 + (n0 & 63) * 2);
                    *(uint32_t*)(arena + off) = cvt2h(v0, v1);
                }
            }
    }

    // ================= GEMM2: out[128x1024] = H[128x256] @ W2 (16 merged stages) =====
    uint32_t boff2[2];
#pragma unroll
    for (int j2 = 0; j2 < 2; j2++)
        boff2[j2] = (uint32_t)(warpN * 32 + j2 * 16 + brow) * 128 + bkoff;

    float acc2[2][4][4];

    for (int s = 0; s < 16; s++) {
        int np = s >> 1;
        if (s == 15) cp_wait0(); else cp_wait1();
        __syncthreads();
        if (s + 2 < 16) { stage2m(s + 2, b2base + 32768u * ((s + 2) % 3)); cp_commit(); }

        if ((s & 1) == 0) {
#pragma unroll
            for (int i = 0; i < 2; i++)
#pragma unroll
                for (int j = 0; j < 4; j++)
#pragma unroll
                    for (int q = 0; q < 4; q++) acc2[i][j][q] = 0.0f;
        }

        uint32_t cbb = b2base + 32768u * (s % 3);
#pragma unroll
        for (int sub = 0; sub < 2; sub++) {
            int kc = (s & 1) * 2 + sub;
            uint32_t ah = sb + kc * 16384;
            uint32_t cb = cbb + sub * 16384;
#pragma unroll
            for (int ks = 0; ks < 4; ks++) {
                uint32_t Ah[2][4];
#pragma unroll
                for (int i = 0; i < 2; i++)
                    ldsm4(Ah[i], ah + sw(aoff[i] + ks * 32));
#pragma unroll
                for (int j2 = 0; j2 < 2; j2++) {
                    uint32_t Bh[4];
                    ldsm4(Bh, cb + sw(boff2[j2] + ks * 32));
#pragma unroll
                    for (int i = 0; i < 2; i++) {
                        mma_h(acc2[i][2 * j2],     Ah[i], Bh[0], Bh[1]);
                        mma_h(acc2[i][2 * j2 + 1], Ah[i], Bh[2], Bh[3]);
                    }
                }
            }
        }

        if (s & 1) {
            // epilogue 2: weighted bias-add -> per-slot fp16 buffer
            int mb = warpM * 32, nb = warpN * 32;
#pragma unroll
            for (int i = 0; i < 2; i++)
#pragma unroll
                for (int j = 0; j < 4; j++) {
                    int m0 = mb + i * 16 + (lane >> 2);
                    int n0 = np * 128 + nb + j * 8 + (lane & 3) * 2;
                    float bb0 = b2s[n0], bb1 = b2s[n0 + 1];
#pragma unroll
                    for (int hr = 0; hr < 2; hr++) {
                        int m = m0 + hr * 8;
                        if (base + m < cnt) {
                            int   tok  = toks[m];
                            float wgt  = twt[m];
                            float o0 = wgt * (acc2[i][j][hr * 2]     + bb0);
                            float o1 = wgt * (acc2[i][j][hr * 2 + 1] + bb1);
                            uint32_t* dst = (uint32_t*)((char*)g_bufh +
                                ((size_t)tslot[m] * BD + (size_t)tok * Dn + n0) * 2);
                            *dst = cvt2h(o0, o1);
                        }
                    }
                }
        }
    }
}

// ---------------- kernel: combine the two fp16 slots -> fp32 out ----------------
__global__ void combine_kernel(float* __restrict__ out) {
    size_t i = ((size_t)blockIdx.x * 512 + threadIdx.x) * 4;
    uint2 pa = *(const uint2*)((const char*)g_bufh + i * 2);
    uint2 pb = *(const uint2*)((const char*)g_bufh + ((size_t)BD + i) * 2);
    __half2 a0 = *(__half2*)&pa.x, a1 = *(__half2*)&pa.y;
    __half2 b0 = *(__half2*)&pb.x, b1 = *(__half2*)&pb.y;
    float2 fa0 = __half22float2(a0), fa1 = __half22float2(a1);
    float2 fb0 = __half22float2(b0), fb1 = __half22float2(b1);
    *(float4*)(out + i) = make_float4(fa0.x + fb0.x, fa0.y + fb0.y,
                                      fa1.x + fb1.x, fa1.y + fb1.y);
}

// ---------------- launch ----------------
extern "C" void kernel_launch(void* const* d_in, const int* in_sizes, int n_in,
                              void* d_out, int out_size) {
    const float* x  = (const float*)d_in[0];
    const float* Wr = (const float*)d_in[1];
    const float* br = (const float*)d_in[2];
    const float* W1 = (const float*)d_in[3];
    const float* b1 = (const float*)d_in[4];
    const float* W2 = (const float*)d_in[5];
    const float* b2 = (const float*)d_in[6];
    float* out = (float*)d_out;

    static cudaStream_t s_side = nullptr;
    static cudaEvent_t  ev_fork = nullptr, ev_join = nullptr,
                        ev_rt = nullptr, ev_aux = nullptr;
    if (!s_side) {
        cudaStreamCreateWithFlags(&s_side, cudaStreamNonBlocking);
        cudaEventCreateWithFlags(&ev_fork, cudaEventDisableTiming);
        cudaEventCreateWithFlags(&ev_join, cudaEventDisableTiming);
        cudaEventCreateWithFlags(&ev_rt,   cudaEventDisableTiming);
        cudaEventCreateWithFlags(&ev_aux,  cudaEventDisableTiming);
    }

    cudaFuncSetAttribute(expert_kernel,
                         cudaFuncAttributeMaxDynamicSharedMemorySize, ARENA_BYTES);

    prep_small<<<(Dn * En + 255) / 256, 256>>>(Wr);

    cudaEventRecord(ev_fork, 0);
    cudaStreamWaitEvent(s_side, ev_fork, 0);
    transpose_half_kernel<<<dim3(8, 32, En), dim3(32, 8), 0, s_side>>>(W1, Dn, Hn, 0);
    transpose_half_kernel<<<dim3(32, 8, En), dim3(32, 8), 0, s_side>>>(W2, Hn, Dn, 1);
    cudaEventRecord(ev_join, s_side);

    router_split_kernel<<<Bn / 8, 256>>>(x, br);
    cudaEventRecord(ev_rt, 0);

    if (out_size > BD) {
        cudaStreamWaitEvent(s_side, ev_rt, 0);
        aux_kernel<<<1, 1, 0, s_side>>>(out + (size_t)BD);
    }
    cudaEventRecord(ev_aux, s_side);

    cudaStreamWaitEvent(0, ev_join, 0);
    expert_kernel<<<dim3(Bn / TMk, En), 512, ARENA_BYTES>>>(b1, b2);
    combine_kernel<<<BD / 2048, 512>>>(out);
    cudaStreamWaitEvent(0, ev_aux, 0);
}

// round 17
// speedup vs baseline: 1.1261x; 1.0002x over previous
#include <cuda_runtime.h>
#include <cuda_fp16.h>
#include <math.h>
#include <stdint.h>

// Problem constants
#define Bn 16384
#define Dn 1024
#define En 6
#define Hn 256
#define TMk 128
#define BD 16777216

// ---------------- device scratch ----------------
__device__ double g_load_sums[En];
__device__ int    g_expert_count[En];
__device__ int    g_expert_tok[En * Bn];   // token | (slot<<30)
__device__ float  g_expert_wt[En * Bn];
__device__ float  g_WrT[En * Dn];          // router weight transposed [e][d]
__device__ __half g_Xh[Bn * Dn];           // x (fp16)
__device__ __half g_W1T[En * Hn * Dn];     // [e][h][d]  (K-major, n=h)
__device__ __half g_W2T[En * Dn * Hn];     // [e][d][h]  (K-major, n=d)
__device__ __half g_bufh[2u * Bn * Dn];    // per-slot weighted expert outputs (fp16)

// ---------------- helpers ----------------
__device__ __forceinline__ uint32_t smem_u32(const void* p) {
    uint32_t a;
    asm("{ .reg .u64 t; cvta.to.shared.u64 t, %1; cvt.u32.u64 %0, t; }" : "=r"(a) : "l"(p));
    return a;
}
__device__ __forceinline__ uint32_t sw(uint32_t o) { return o ^ ((o >> 3) & 0x70); }
__device__ __forceinline__ uint32_t cvt2h(float lo, float hi) {
    uint32_t r;
    asm("cvt.rn.f16x2.f32 %0, %1, %2;" : "=r"(r) : "f"(hi), "f"(lo));
    return r;
}
__device__ __forceinline__ void ldsm4(uint32_t* r, uint32_t a) {
    asm volatile("ldmatrix.sync.aligned.m8n8.x4.shared.b16 {%0,%1,%2,%3}, [%4];"
                 : "=r"(r[0]), "=r"(r[1]), "=r"(r[2]), "=r"(r[3]) : "r"(a));
}
__device__ __forceinline__ void mma_h(float* c, const uint32_t* a, uint32_t b0, uint32_t b1) {
    asm volatile(
        "mma.sync.aligned.m16n8k16.row.col.f32.f16.f16.f32 "
        "{%0,%1,%2,%3}, {%4,%5,%6,%7}, {%8,%9}, {%0,%1,%2,%3};"
        : "+f"(c[0]), "+f"(c[1]), "+f"(c[2]), "+f"(c[3])
        : "r"(a[0]), "r"(a[1]), "r"(a[2]), "r"(a[3]), "r"(b0), "r"(b1));
}
__device__ __forceinline__ void cpa(uint32_t dst, const void* src) {
    asm volatile("cp.async.cg.shared.global [%0], [%1], 16;" :: "r"(dst), "l"(src));
}
__device__ __forceinline__ void cp_commit() { asm volatile("cp.async.commit_group;"); }
__device__ __forceinline__ void cp_wait0()  { asm volatile("cp.async.wait_group 0;"); }
__device__ __forceinline__ void cp_wait1()  { asm volatile("cp.async.wait_group 1;"); }
__device__ __forceinline__ float gelu(float t) {
    return 0.5f * t * (1.0f + erff(t * 0.70710678118654752f));
}

// ---------------- kernel: zero counters + transpose Wr ----------------
__global__ void prep_small(const float* __restrict__ Wr) {
    int i = blockIdx.x * 256 + threadIdx.x;
    if (i < En) {
        g_load_sums[i] = 0.0;
        g_expert_count[i] = 0;
    }
    if (i < Dn * En) {
        int d = i / En, e = i % En;
        g_WrT[e * Dn + d] = Wr[i];
    }
}

// ---------------- kernel: weight transpose -> fp16 ----------------
__global__ void transpose_half_kernel(const float* __restrict__ src, int R, int C, int which) {
    __shared__ float tile[32][33];
    int e = blockIdx.z;
    int c0 = blockIdx.x * 32, r0 = blockIdx.y * 32;
    const float* s = src + (size_t)e * R * C;
    __half* d = (which == 0 ? g_W1T : g_W2T) + (size_t)e * R * C;
#pragma unroll
    for (int i = 0; i < 32; i += 8)
        tile[threadIdx.y + i][threadIdx.x] = s[(size_t)(r0 + threadIdx.y + i) * C + c0 + threadIdx.x];
    __syncthreads();
#pragma unroll
    for (int i = 0; i < 32; i += 8) {
        size_t o = (size_t)(c0 + threadIdx.y + i) * R + r0 + threadIdx.x;
        d[o] = __float2half_rn(tile[threadIdx.x][threadIdx.y + i]);
    }
}

// ---------------- kernel: fused router + x->fp16, block-aggregated atomics ----------------
// 256 threads = 8 warps = 8 tokens/block, grid Bn/8; 4 blocks/SM (32 warps).
__global__ void __launch_bounds__(256, 4) router_split_kernel(
    const float* __restrict__ x, const float* __restrict__ br)
{
    __shared__ float wsh[En * Dn];        // 24KB
    __shared__ float sm_p[8][En];
    __shared__ int   sm_pick[8][2];
    __shared__ float sm_w[8][2];

    int tid = threadIdx.x;
    int warp = tid >> 5, lane = tid & 31;
    for (int i = tid * 4; i < En * Dn; i += 1024)
        *(float4*)(wsh + i) = *(const float4*)(g_WrT + i);
    __syncthreads();

    int t = blockIdx.x * 8 + warp;
    {
        const float* xr = x + (size_t)t * Dn;
        char* dh = (char*)g_Xh + (size_t)t * Dn * 2;

        float acc[En];
#pragma unroll
        for (int e = 0; e < En; e++) acc[e] = 0.0f;

#pragma unroll
        for (int half = 0; half < 2; half++) {
            float4 v[4];
#pragma unroll
            for (int jj = 0; jj < 4; jj++)
                v[jj] = *(const float4*)(xr + (lane + 32 * (half * 4 + jj)) * 4);
#pragma unroll
            for (int jj = 0; jj < 4; jj++) {
                int d0 = (lane + 32 * (half * 4 + jj)) * 4;
#pragma unroll
                for (int e = 0; e < En; e++) {
                    float4 w = *(const float4*)(wsh + e * Dn + d0);
                    acc[e] = fmaf(v[jj].x, w.x, acc[e]);
                    acc[e] = fmaf(v[jj].y, w.y, acc[e]);
                    acc[e] = fmaf(v[jj].z, w.z, acc[e]);
                    acc[e] = fmaf(v[jj].w, w.w, acc[e]);
                }
                *(uint2*)(dh + d0 * 2) = make_uint2(cvt2h(v[jj].x, v[jj].y),
                                                    cvt2h(v[jj].z, v[jj].w));
            }
        }
#pragma unroll
        for (int off = 16; off > 0; off >>= 1)
#pragma unroll
            for (int e = 0; e < En; e++)
                acc[e] += __shfl_xor_sync(0xffffffffu, acc[e], off);

        if (lane == 0) {
            float p[En];
            float m = -1e30f;
#pragma unroll
            for (int e = 0; e < En; e++) { p[e] = acc[e] + br[e]; m = fmaxf(m, p[e]); }
            float s = 0.0f;
#pragma unroll
            for (int e = 0; e < En; e++) { p[e] = expf(p[e] - m); s += p[e]; }
            float inv = 1.0f / s;
#pragma unroll
            for (int e = 0; e < En; e++) {
                p[e] = 0.9f * p[e] * inv + (0.1f / 6.0f);
                sm_p[warp][e] = p[e];
            }
            int i0 = 0;
#pragma unroll
            for (int e = 1; e < En; e++) if (p[e] > p[i0]) i0 = e;
            int i1 = (i0 == 0) ? 1 : 0;
#pragma unroll
            for (int e = 0; e < En; e++) if (e != i0 && p[e] > p[i1]) i1 = e;
            sm_pick[warp][0] = i0; sm_pick[warp][1] = i1;
            sm_w[warp][0] = p[i0]; sm_w[warp][1] = p[i1];
        }
    }
    __syncthreads();

    if (tid < En) {
        int e = tid;
        double s = 0.0;
        int cnt = 0;
#pragma unroll
        for (int w = 0; w < 8; w++) {
            s += (double)sm_p[w][e];
            cnt += (sm_pick[w][0] == e) + (sm_pick[w][1] == e);
        }
        atomicAdd(&g_load_sums[e], s);
        int base = atomicAdd(&g_expert_count[e], cnt);
#pragma unroll
        for (int w = 0; w < 8; w++) {
            int tt = blockIdx.x * 8 + w;
            if (sm_pick[w][0] == e) {
                g_expert_tok[e * Bn + base] = tt;
                g_expert_wt[e * Bn + base] = sm_w[w][0];
                base++;
            }
            if (sm_pick[w][1] == e) {
                g_expert_tok[e * Bn + base] = tt | (1 << 30);
                g_expert_wt[e * Bn + base] = sm_w[w][1];
                base++;
            }
        }
    }
}

// ---------------- kernel: aux scalar ----------------
__global__ void aux_kernel(float* __restrict__ out_aux) {
    double aux = 0.0;
#pragma unroll
    for (int e = 0; e < En; e++) {
        double load = g_load_sums[e] / (double)Bn;
        aux += load * log(load * (double)En + 1e-9);
    }
    out_aux[0] = (float)(aux / log((double)En + 1e-9));
}

// ---------------- kernel: expert MLP (R13 config: 512 thr, 16 warps, 32x64 tile) ----------------
// Arena (160KB + pad):
//  GEMM1 (3-stage): B(c) = sb + 49152*(c%3): Xh+0(16K) W+16384(32K)
//  H panels (post-GEMM1): 4 x 16K at sb+0..65535
//  GEMM2 (3 x 32K merged-kc stages): C(s) = sb + 65536 + 32768*(s%3)
#define ARENA_BYTES (163840 + 1024)
extern __shared__ char dsm[];

__global__ void __launch_bounds__(512, 1) expert_kernel(
    const float* __restrict__ b1g, const float* __restrict__ b2g)
{
    __shared__ int   toks[TMk];
    __shared__ int   tslot[TMk];
    __shared__ float twt[TMk];
    __shared__ float b1s[Hn];
    __shared__ float b2s[Dn];

    int e = blockIdx.y;
    int cnt = g_expert_count[e];
    int base = blockIdx.x * TMk;
    if (base >= cnt) return;

    int tid = threadIdx.x;
    int wid = tid >> 5, lane = tid & 31;

    uint32_t raw = smem_u32(dsm);
    uint32_t sb  = (raw + 1023u) & ~1023u;
    char* arena  = dsm + (sb - raw);

    if (tid < TMk) {
        int i = base + tid;
        if (i < cnt) {
            int v = g_expert_tok[e * Bn + i];
            toks[tid] = v & 0x3FFFFFFF; tslot[tid] = v >> 30;
            twt[tid] = g_expert_wt[e * Bn + i];
        } else { toks[tid] = 0; tslot[tid] = 0; twt[tid] = 0.0f; }
    }
    if (tid < Hn) b1s[tid] = b1g[e * Hn + tid];
    for (int f = tid; f < Dn; f += 512) b2s[f] = b2g[e * Dn + f];
    __syncthreads();

    // ---- fragment address constants ----
    int g  = lane >> 3, r = lane & 7;
    int arow = (g & 1) * 8 + r, akoff = (g >> 1) * 16;
    int brow = (g >> 1) * 8 + r, bkoff = (g & 1) * 16;
    int warpM = wid & 3, warpN = wid >> 2;

    uint32_t aoff[2];
    aoff[0] = (uint32_t)(warpM * 32 + arow) * 128 + akoff;
    aoff[1] = aoff[0] + 16 * 128;
    uint32_t boff1[4];
#pragma unroll
    for (int j2 = 0; j2 < 4; j2++)
        boff1[j2] = (uint32_t)(warpN * 64 + j2 * 16 + brow) * 128 + bkoff;

    // ---- staging tables ----
    const char* srcX[2]; uint32_t dstX[2];
#pragma unroll
    for (int p = 0; p < 2; p++) {
        int f = tid + p * 512, row = f >> 3, seg = f & 7;
        srcX[p] = (const char*)(g_Xh + (size_t)toks[row] * Dn) + seg * 16;
        dstX[p] = sw((uint32_t)row * 128 + seg * 16);
    }
    const __half* W1t = g_W1T + (size_t)e * Hn * Dn;
    const char* srcW[4]; uint32_t dstW[4];
#pragma unroll
    for (int p = 0; p < 4; p++) {
        int f = tid + p * 512, row = f >> 3, seg = f & 7;
        srcW[p] = (const char*)(W1t + (size_t)row * Dn) + seg * 16;
        dstW[p] = sw((uint32_t)row * 128 + seg * 16);
    }

    auto stage1 = [&](int ci, uint32_t bb) {
        uint32_t o = (uint32_t)ci * 128;
#pragma unroll
        for (int p = 0; p < 2; p++)
            cpa(bb + dstX[p], srcX[p] + o);
#pragma unroll
        for (int p = 0; p < 4; p++)
            cpa(bb + 16384 + dstW[p], srcW[p] + o);
    };

    // ================= GEMM1: C1[128x256] = X[128x1024] @ W1 (3-stage) =========
    float acc[2][8][4];
#pragma unroll
    for (int i = 0; i < 2; i++)
#pragma unroll
        for (int j = 0; j < 8; j++)
#pragma unroll
            for (int q = 0; q < 4; q++) acc[i][j][q] = 0.0f;

    stage1(0, sb);         cp_commit();
    stage1(1, sb + 49152); cp_commit();

    for (int ci = 0; ci < 16; ci++) {
        if (ci == 15) cp_wait0(); else cp_wait1();
        __syncthreads();
        if (ci + 2 < 16) { stage1(ci + 2, sb + 49152u * ((ci + 2) % 3)); cp_commit(); }

        uint32_t cb = sb + 49152u * (ci % 3);
        uint32_t xh = cb, wh = cb + 16384;
#pragma unroll
        for (int ks = 0; ks < 4; ks++) {
            uint32_t Ah[2][4];
#pragma unroll
            for (int i = 0; i < 2; i++)
                ldsm4(Ah[i], xh + sw(aoff[i] + ks * 32));
#pragma unroll
            for (int j2 = 0; j2 < 4; j2++) {
                uint32_t Bh[4];
                ldsm4(Bh, wh + sw(boff1[j2] + ks * 32));
#pragma unroll
                for (int i = 0; i < 2; i++) {
                    mma_h(acc[i][2 * j2],     Ah[i], Bh[0], Bh[1]);
                    mma_h(acc[i][2 * j2 + 1], Ah[i], Bh[2], Bh[3]);
                }
            }
        }
    }
    __syncthreads();   // all GEMM1 reads done before H/GEMM2 staging overwrites arena

    // ---- GEMM2 staging (merged kc-pairs: 32KB per stage, 3 buffers) ----
    const __half* W2t = g_W2T + (size_t)e * Dn * Hn;
    uint32_t srcO2[2], dst2[2];
#pragma unroll
    for (int p = 0; p < 2; p++) {
        int f = tid + p * 512, row = f >> 3, seg = f & 7;
        srcO2[p] = (uint32_t)row * 512 + seg * 16;
        dst2[p]  = sw((uint32_t)row * 128 + seg * 16);
    }
    auto stage2m = [&](int s, uint32_t bb) {
        int np = s >> 1;
#pragma unroll
        for (int sub = 0; sub < 2; sub++) {
            int kc = (s & 1) * 2 + sub;
            uint32_t o = (uint32_t)np * 65536 + (uint32_t)kc * 128;
#pragma unroll
            for (int p = 0; p < 2; p++)
                cpa(bb + sub * 16384 + dst2[p], (const char*)W2t + srcO2[p] + o);
        }
    };
    uint32_t b2base = sb + 65536;
    stage2m(0, b2base);          cp_commit();
    stage2m(1, b2base + 32768);  cp_commit();

    // ---- epilogue 1: bias + GELU -> fp16 H panels ----
    {
        int mb = warpM * 32, nb = warpN * 64;
#pragma unroll
        for (int i = 0; i < 2; i++)
#pragma unroll
            for (int j = 0; j < 8; j++) {
                int m0 = mb + i * 16 + (lane >> 2);
                int n0 = nb + j * 8 + (lane & 3) * 2;
                float bb0 = b1s[n0], bb1 = b1s[n0 + 1];
#pragma unroll
                for (int hr = 0; hr < 2; hr++) {
                    int m = m0 + hr * 8;
                    float v0 = gelu(acc[i][j][hr * 2]     + bb0);
                    float v1 = gelu(acc[i][j][hr * 2 + 1] + bb1);
                    uint32_t off = ((uint32_t)(n0 >> 6)) * 16384 + sw((uint32_t)m * 128 + (n0 & 63) * 2);
                    *(uint32_t*)(arena + off) = cvt2h(v0, v1);
                }
            }
    }

    // ================= GEMM2: out[128x1024] = H[128x256] @ W2 (16 merged stages) =====
    uint32_t boff2[2];
#pragma unroll
    for (int j2 = 0; j2 < 2; j2++)
        boff2[j2] = (uint32_t)(warpN * 32 + j2 * 16 + brow) * 128 + bkoff;

    float acc2[2][4][4];

    for (int s = 0; s < 16; s++) {
        int np = s >> 1;
        if (s == 15) cp_wait0(); else cp_wait1();
        __syncthreads();
        if (s + 2 < 16) { stage2m(s + 2, b2base + 32768u * ((s + 2) % 3)); cp_commit(); }

        if ((s & 1) == 0) {
#pragma unroll
            for (int i = 0; i < 2; i++)
#pragma unroll
                for (int j = 0; j < 4; j++)
#pragma unroll
                    for (int q = 0; q < 4; q++) acc2[i][j][q] = 0.0f;
        }

        uint32_t cbb = b2base + 32768u * (s % 3);
#pragma unroll
        for (int sub = 0; sub < 2; sub++) {
            int kc = (s & 1) * 2 + sub;
            uint32_t ah = sb + kc * 16384;
            uint32_t cb = cbb + sub * 16384;
#pragma unroll
            for (int ks = 0; ks < 4; ks++) {
                uint32_t Ah[2][4];
#pragma unroll
                for (int i = 0; i < 2; i++)
                    ldsm4(Ah[i], ah + sw(aoff[i] + ks * 32));
#pragma unroll
                for (int j2 = 0; j2 < 2; j2++) {
                    uint32_t Bh[4];
                    ldsm4(Bh, cb + sw(boff2[j2] + ks * 32));
#pragma unroll
                    for (int i = 0; i < 2; i++) {
                        mma_h(acc2[i][2 * j2],     Ah[i], Bh[0], Bh[1]);
                        mma_h(acc2[i][2 * j2 + 1], Ah[i], Bh[2], Bh[3]);
                    }
                }
            }
        }

        if (s & 1) {
            // epilogue 2: weighted bias-add -> per-slot fp16 buffer
            int mb = warpM * 32, nb = warpN * 32;
#pragma unroll
            for (int i = 0; i < 2; i++)
#pragma unroll
                for (int j = 0; j < 4; j++) {
                    int m0 = mb + i * 16 + (lane >> 2);
                    int n0 = np * 128 + nb + j * 8 + (lane & 3) * 2;
                    float bb0 = b2s[n0], bb1 = b2s[n0 + 1];
#pragma unroll
                    for (int hr = 0; hr < 2; hr++) {
                        int m = m0 + hr * 8;
                        if (base + m < cnt) {
                            int   tok  = toks[m];
                            float wgt  = twt[m];
                            float o0 = wgt * (acc2[i][j][hr * 2]     + bb0);
                            float o1 = wgt * (acc2[i][j][hr * 2 + 1] + bb1);
                            uint32_t* dst = (uint32_t*)((char*)g_bufh +
                                ((size_t)tslot[m] * BD + (size_t)tok * Dn + n0) * 2);
                            *dst = cvt2h(o0, o1);
                        }
                    }
                }
        }
    }
}

// ---------------- kernel: combine the two fp16 slots -> fp32 out ----------------
__global__ void combine_kernel(float* __restrict__ out) {
    size_t i = ((size_t)blockIdx.x * 512 + threadIdx.x) * 4;
    uint2 pa = *(const uint2*)((const char*)g_bufh + i * 2);
    uint2 pb = *(const uint2*)((const char*)g_bufh + ((size_t)BD + i) * 2);
    __half2 a0 = *(__half2*)&pa.x, a1 = *(__half2*)&pa.y;
    __half2 b0 = *(__half2*)&pb.x, b1 = *(__half2*)&pb.y;
    float2 fa0 = __half22float2(a0), fa1 = __half22float2(a1);
    float2 fb0 = __half22float2(b0), fb1 = __half22float2(b1);
    *(float4*)(out + i) = make_float4(fa0.x + fb0.x, fa0.y + fb0.y,
                                      fa1.x + fb1.x, fa1.y + fb1.y);
}

// ---------------- launch ----------------
extern "C" void kernel_launch(void* const* d_in, const int* in_sizes, int n_in,
                              void* d_out, int out_size) {
    const float* x  = (const float*)d_in[0];
    const float* Wr = (const float*)d_in[1];
    const float* br = (const float*)d_in[2];
    const float* W1 = (const float*)d_in[3];
    const float* b1 = (const float*)d_in[4];
    const float* W2 = (const float*)d_in[5];
    const float* b2 = (const float*)d_in[6];
    float* out = (float*)d_out;

    static cudaStream_t s_side = nullptr;
    static cudaEvent_t  ev_fork = nullptr, ev_join = nullptr,
                        ev_rt = nullptr, ev_aux = nullptr;
    if (!s_side) {
        cudaStreamCreateWithFlags(&s_side, cudaStreamNonBlocking);
        cudaEventCreateWithFlags(&ev_fork, cudaEventDisableTiming);
        cudaEventCreateWithFlags(&ev_join, cudaEventDisableTiming);
        cudaEventCreateWithFlags(&ev_rt,   cudaEventDisableTiming);
        cudaEventCreateWithFlags(&ev_aux,  cudaEventDisableTiming);
    }

    cudaFuncSetAttribute(expert_kernel,
                         cudaFuncAttributeMaxDynamicSharedMemorySize, ARENA_BYTES);

    prep_small<<<(Dn * En + 255) / 256, 256>>>(Wr);

    cudaEventRecord(ev_fork, 0);
    cudaStreamWaitEvent(s_side, ev_fork, 0);
    transpose_half_kernel<<<dim3(8, 32, En), dim3(32, 8), 0, s_side>>>(W1, Dn, Hn, 0);
    transpose_half_kernel<<<dim3(32, 8, En), dim3(32, 8), 0, s_side>>>(W2, Hn, Dn, 1);
    cudaEventRecord(ev_join, s_side);

    router_split_kernel<<<Bn / 8, 256>>>(x, br);
    cudaEventRecord(ev_rt, 0);

    if (out_size > BD) {
        cudaStreamWaitEvent(s_side, ev_rt, 0);
        aux_kernel<<<1, 1, 0, s_side>>>(out + (size_t)BD);
    }
    cudaEventRecord(ev_aux, s_side);

    cudaStreamWaitEvent(0, ev_join, 0);
    expert_kernel<<<dim3(Bn / TMk, En), 512, ARENA_BYTES>>>(b1, b2);
    combine_kernel<<<BD / 2048, 512>>>(out);
    cudaStreamWaitEvent(0, ev_aux, 0);
}